// round 13
// baseline (speedup 1.0000x reference)
#include <cuda_runtime.h>

// ----------------------------------------------------------------------------
// Decoder_31791347925413 — skin reflectance decoder
//
// Inputs (metadata order):
//  0 lighting      [128,17]          f32
//  1 mel           [128,1,64,64]     f32
//  2 blood         [128,1,64,64]     f32
//  3 shade         [128,1,64,64]     f32
//  4 spec          [128,3,64,64]     f32
//  5 illA          [33]              f32
//  6 illF          [33,12]           f32
//  7 pcaMeans      [99]              f32
//  8 pcaComponents [99,2]            f32
//  9 skinColor     [1,33,256,256]    f32
// 10 tmatrix       [1,9,128,128]     f32
//
// Output: concat of flattened (rgb, shade, spec, blood, mel, b, raw), f32.
// ----------------------------------------------------------------------------

#define NSAMP 128
#define PIX   4096          // 64*64
#define SKW   256
#define TMW   128

// Output region offsets (in elements)
#define OFF_RGB   0
#define OFF_SHADE 1572864
#define OFF_SPEC  2097152
#define OFF_BLOOD 3670016
#define OFF_MEL   4194304
#define OFF_B     4718592
#define OFF_RAW   4718848

__constant__ float c_S0[33] = {
    94.8f,104.8f,105.9f,96.8f,113.9f,125.6f,125.5f,121.3f,121.3f,113.5f,113.1f,
    110.8f,106.5f,108.8f,105.3f,104.4f,100.0f,96.0f,95.1f,89.1f,90.5f,90.3f,
    88.4f,84.0f,85.1f,81.9f,82.6f,84.9f,81.3f,71.9f,74.3f,76.4f,63.3f};
__constant__ float c_S1[33] = {
    43.4f,46.3f,43.9f,37.1f,36.7f,35.9f,32.6f,27.9f,24.3f,20.1f,16.2f,13.2f,
    8.6f,6.1f,4.2f,1.9f,0.0f,-1.6f,-3.5f,-3.5f,-5.8f,-7.2f,-8.6f,-9.5f,-10.9f,
    -10.7f,-12.0f,-14.0f,-13.6f,-12.0f,-13.3f,-12.9f,-10.6f};
__constant__ float c_S2[33] = {
    -1.1f,-0.5f,-0.7f,-1.2f,-2.6f,-2.9f,-2.8f,-2.6f,-2.6f,-1.8f,-1.5f,-1.3f,
    -1.2f,-1.0f,-0.5f,-0.3f,0.0f,0.2f,0.5f,2.1f,3.2f,4.1f,4.7f,5.1f,6.7f,7.3f,
    8.6f,9.8f,10.2f,8.3f,9.6f,8.5f,7.0f};
__constant__ float c_X2R[9] = {
    3.2406f,-1.537f,-0.498f, -0.968f,1.8758f,0.0415f, 0.0557f,-0.204f,1.057f};

// Per-sample folded constants: M[c][k] = e[k]*S[c][k] (padded to 36),
// lightColor[3], A[o][c] = (XYZ2RGB @ T^T)[o][c] / lightColor[c].
// Exactly 120 floats, copied flat into shared memory by the main kernel.
struct SampleConst {
    float M[3][36];   // 108
    float lc[3];      // 3
    float A[9];       // 9  (A[o*3+c])
};
__device__ SampleConst g_sc[NSAMP];

// skinColor transposed to channel-minor: [256][256][36] floats (36 = pad of 33)
__device__ float4 g_tab[SKW * SKW * 9];

__device__ __forceinline__ float sigmoidf_(float v) {
    return 1.0f / (1.0f + expf(-v));
}

// ---------------------------------------------------------------------------
// Kernel A: per-sample scalar constants (1 block, 128 threads, 1 thread/sample)
// ---------------------------------------------------------------------------
__global__ void setup_kernel(const float* __restrict__ lighting,
                             const float* __restrict__ illA,
                             const float* __restrict__ illF,
                             const float* __restrict__ pcaMeans,
                             const float* __restrict__ pcaComp,
                             const float* __restrict__ tmatrix,
                             float* __restrict__ out)
{
    int n = threadIdx.x;
    if (n >= NSAMP) return;
    const float* L = lighting + n * 17;

    // softmax over lp[0:14]
    float lp[15];
    #pragma unroll
    for (int i = 0; i < 15; i++) lp[i] = L[i];
    float mx = lp[0];
    #pragma unroll
    for (int i = 1; i < 14; i++) mx = fmaxf(mx, lp[i]);
    float ex[14], ssum = 0.0f;
    #pragma unroll
    for (int i = 0; i < 14; i++) { ex[i] = expf(lp[i] - mx); ssum += ex[i]; }
    float sinv = 1.0f / ssum;
    float wA = ex[0] * sinv;
    float wD = ex[1] * sinv;
    float fW[12];
    #pragma unroll
    for (int j = 0; j < 12; j++) fW[j] = ex[2 + j] * sinv;

    float ct = sigmoidf_(lp[14]);
    float b0 = 6.0f * sigmoidf_(L[15]) - 3.0f;
    float b1 = 6.0f * sigmoidf_(L[16]) - 3.0f;
    out[OFF_B + n * 2 + 0] = b0;
    out[OFF_B + n * 2 + 1] = b1;

    // illuminance_d
    float t = ct * 21000.0f + 4000.0f;
    float t2 = t * t, t3 = t2 * t;
    float x;
    if (t <= 7000.0f)
        x = -4.607e9f / t3 + 2.9678e6f / t2 + 99.11f / t + 0.244063f;
    else
        x = -2.0064e9f / t3 + 1.9018e6f / t2 + 247.48f / t + 0.23704f;
    float y  = -3.0f * x * x + 2.87f * x - 0.275f;
    float mm = 0.0241f + 0.2562f * x - 0.7341f * y;
    float m1 = (-1.3515f - 1.7703f * x + 5.9114f * y) / mm;
    float m2 = (0.03f - 31.4424f * x + 30.0717f * y) / mm;

    float dd[33], dsum = 0.0f;
    #pragma unroll
    for (int k = 0; k < 33; k++) {
        dd[k] = c_S0[k] + m1 * c_S1[k] + m2 * c_S2[k];
        dsum += dd[k];
    }
    float dinv = 1.0f / dsum;

    float e[33], esum = 0.0f;
    #pragma unroll
    for (int k = 0; k < 33; k++) {
        float v = wA * illA[k] + wD * dd[k] * dinv;
        #pragma unroll
        for (int j = 0; j < 12; j++) v += fW[j] * illF[k * 12 + j];
        e[k] = v;
        esum += v;
    }
    float einv = 1.0f / esum;

    // S = relu(b @ pcaComponents.T + pcaMeans), reshape (3,33)
    float S[99];
    float lc[3] = {0.0f, 0.0f, 0.0f};
    #pragma unroll 3
    for (int i = 0; i < 99; i++) {
        float v = pcaMeans[i] + b0 * pcaComp[i * 2] + b1 * pcaComp[i * 2 + 1];
        v = fmaxf(v, 0.0f);
        S[i] = v;
        lc[i / 33] += v;
    }

    SampleConst* sc = &g_sc[n];
    #pragma unroll
    for (int c = 0; c < 3; c++) {
        #pragma unroll
        for (int k = 0; k < 33; k++)
            sc->M[c][k] = e[k] * einv * S[c * 33 + k];
        sc->M[c][33] = 0.0f; sc->M[c][34] = 0.0f; sc->M[c][35] = 0.0f;
        sc->lc[c] = lc[c];
    }

    // bilinear sample of tmatrix at (b/3) -> T[3][3]
    float gx = (b0 * (1.0f / 3.0f) + 1.0f) * 0.5f * 127.0f;
    float gy = (b1 * (1.0f / 3.0f) + 1.0f) * 0.5f * 127.0f;
    float x0f = floorf(gx), y0f = floorf(gy);
    float wx = gx - x0f, wy = gy - y0f;
    int x0 = min(max((int)x0f, 0), 127);
    int y0 = min(max((int)y0f, 0), 127);
    int x1 = min(x0 + 1, 127);
    int y1 = min(y0 + 1, 127);
    float w00 = (1.0f - wx) * (1.0f - wy);
    float w01 = wx * (1.0f - wy);
    float w10 = (1.0f - wx) * wy;
    float w11 = wx * wy;

    float T[9];
    #pragma unroll
    for (int ch = 0; ch < 9; ch++) {
        const float* im = tmatrix + ch * TMW * TMW;
        float v00 = im[y0 * TMW + x0];
        float v01 = im[y0 * TMW + x1];
        float v10 = im[y1 * TMW + x0];
        float v11 = im[y1 * TMW + x1];
        T[ch] = v00 * w00 + v01 * w01 + v10 * w10 + v11 * w11;
    }
    // A[o][c] = (sum_j X2R[o][j] * T[c][j]) / lc[c]
    #pragma unroll
    for (int o = 0; o < 3; o++) {
        #pragma unroll
        for (int c = 0; c < 3; c++) {
            float v = c_X2R[o * 3 + 0] * T[c * 3 + 0]
                    + c_X2R[o * 3 + 1] * T[c * 3 + 1]
                    + c_X2R[o * 3 + 2] * T[c * 3 + 2];
            sc->A[o * 3 + c] = v / lc[c];
        }
    }
}

// ---------------------------------------------------------------------------
// Kernel B: transpose skinColor [33,256,256] -> [256,256,36] (channel-minor)
// ---------------------------------------------------------------------------
__global__ void transpose_kernel(const float* __restrict__ skin)
{
    int x = threadIdx.x;   // 0..255 (coalesced reads along x)
    int y = blockIdx.x;    // 0..255
    float v[36];
    #pragma unroll
    for (int k = 0; k < 33; k++)
        v[k] = skin[k * (SKW * SKW) + y * SKW + x];
    v[33] = 0.0f; v[34] = 0.0f; v[35] = 0.0f;
    float4* dst = &g_tab[(y * SKW + x) * 9];
    #pragma unroll
    for (int q = 0; q < 9; q++)
        dst[q] = make_float4(v[4*q], v[4*q+1], v[4*q+2], v[4*q+3]);
}

// ---------------------------------------------------------------------------
// Kernel C: per-pixel main. 16 blocks of 256 threads per sample.
// ---------------------------------------------------------------------------
__global__ void __launch_bounds__(256) main_kernel(
    const float* __restrict__ mel,
    const float* __restrict__ blood,
    const float* __restrict__ shade,
    const float* __restrict__ spec,
    float* __restrict__ out)
{
    __shared__ float sc[120];   // M[3][36] | lc[3] | A[9]
    int n = blockIdx.x >> 4;
    int p = ((blockIdx.x & 15) << 8) + threadIdx.x;

    if (threadIdx.x < 120)
        sc[threadIdx.x] = ((const float*)&g_sc[n])[threadIdx.x];
    __syncthreads();

    int gi = n * PIX + p;
    float mraw = mel[gi];
    float braw = blood[gi];
    float sm = sigmoidf_(mraw);
    float sb = sigmoidf_(braw);
    float ms = 2.0f * sm - 1.0f;
    float bs = 2.0f * sb - 1.0f;
    float sh = expf(shade[gi]);

    // grid coords into 256x256 table: x = sigmoid(mel)*255, y = sigmoid(blood)*255
    float x = sm * 255.0f;
    float y = sb * 255.0f;
    float x0f = floorf(x), y0f = floorf(y);
    float wx = x - x0f, wy = y - y0f;
    int x0 = min(max((int)x0f, 0), 255);
    int y0 = min(max((int)y0f, 0), 255);
    int x1 = min(x0 + 1, 255);
    int y1 = min(y0 + 1, 255);
    float w00 = (1.0f - wx) * (1.0f - wy);
    float w01 = wx * (1.0f - wy);
    float w10 = (1.0f - wx) * wy;
    float w11 = wx * wy;

    const float4* t00 = &g_tab[(y0 * SKW + x0) * 9];
    const float4* t01 = &g_tab[(y0 * SKW + x1) * 9];
    const float4* t10 = &g_tab[(y1 * SKW + x0) * 9];
    const float4* t11 = &g_tab[(y1 * SKW + x1) * 9];

    float d0 = 0.0f, d1 = 0.0f, d2 = 0.0f;
    #pragma unroll
    for (int q = 0; q < 9; q++) {
        float4 a = __ldg(t00 + q);
        float4 b = __ldg(t01 + q);
        float4 c = __ldg(t10 + q);
        float4 e = __ldg(t11 + q);
        float rx = w00 * a.x + w01 * b.x + w10 * c.x + w11 * e.x;
        float ry = w00 * a.y + w01 * b.y + w10 * c.y + w11 * e.y;
        float rz = w00 * a.z + w01 * b.z + w10 * c.z + w11 * e.z;
        float rw = w00 * a.w + w01 * b.w + w10 * c.w + w11 * e.w;
        int k = 4 * q;
        d0 += rx * sc[0*36 + k] + ry * sc[0*36 + k+1] + rz * sc[0*36 + k+2] + rw * sc[0*36 + k+3];
        d1 += rx * sc[1*36 + k] + ry * sc[1*36 + k+1] + rz * sc[1*36 + k+2] + rw * sc[1*36 + k+3];
        d2 += rx * sc[2*36 + k] + ry * sc[2*36 + k+1] + rz * sc[2*36 + k+2] + rw * sc[2*36 + k+3];
    }
    d0 *= sh; d1 *= sh; d2 *= sh;

    float lc0 = sc[108], lc1 = sc[109], lc2 = sc[110];
    float sp0 = expf(spec[(n * 3 + 0) * PIX + p]) * lc0;
    float sp1 = expf(spec[(n * 3 + 1) * PIX + p]) * lc1;
    float sp2 = expf(spec[(n * 3 + 2) * PIX + p]) * lc2;

    float r0 = d0 + sp0;
    float r1 = d1 + sp1;
    float r2 = d2 + sp2;

    float g0 = fmaxf(sc[111] * r0 + sc[112] * r1 + sc[113] * r2, 0.0f);
    float g1 = fmaxf(sc[114] * r0 + sc[115] * r1 + sc[116] * r2, 0.0f);
    float g2 = fmaxf(sc[117] * r0 + sc[118] * r1 + sc[119] * r2, 0.0f);

    int c3 = n * 3 * PIX + p;
    // rgb
    out[OFF_RGB + c3]            = g0;
    out[OFF_RGB + c3 + PIX]      = g1;
    out[OFF_RGB + c3 + 2 * PIX]  = g2;
    // shade (exp)
    out[OFF_SHADE + gi] = sh;
    // spec (scaled)
    out[OFF_SPEC + c3]           = sp0;
    out[OFF_SPEC + c3 + PIX]     = sp1;
    out[OFF_SPEC + c3 + 2 * PIX] = sp2;
    // blood, mel (squashed)
    out[OFF_BLOOD + gi] = bs;
    out[OFF_MEL + gi]   = ms;
    // raw
    out[OFF_RAW + c3]            = r0;
    out[OFF_RAW + c3 + PIX]      = r1;
    out[OFF_RAW + c3 + 2 * PIX]  = r2;
}

// ---------------------------------------------------------------------------
extern "C" void kernel_launch(void* const* d_in, const int* in_sizes, int n_in,
                              void* d_out, int out_size)
{
    const float* lighting = (const float*)d_in[0];
    const float* mel      = (const float*)d_in[1];
    const float* blood    = (const float*)d_in[2];
    const float* shade    = (const float*)d_in[3];
    const float* spec     = (const float*)d_in[4];
    const float* illA     = (const float*)d_in[5];
    const float* illF     = (const float*)d_in[6];
    const float* pcaMeans = (const float*)d_in[7];
    const float* pcaComp  = (const float*)d_in[8];
    const float* skin     = (const float*)d_in[9];
    const float* tmatrix  = (const float*)d_in[10];
    float* out = (float*)d_out;

    setup_kernel<<<1, 128>>>(lighting, illA, illF, pcaMeans, pcaComp, tmatrix, out);
    transpose_kernel<<<256, 256>>>(skin);
    main_kernel<<<(NSAMP * PIX) / 256, 256>>>(mel, blood, shade, spec, out);
}

// round 14
// speedup vs baseline: 2.0351x; 2.0351x over previous
#include <cuda_runtime.h>
#include <cuda_fp16.h>

// ----------------------------------------------------------------------------
// Decoder_31791347925413 — skin reflectance decoder (R13: parallel setup +
// fp16 channel-minor gather table)
// ----------------------------------------------------------------------------

#define NSAMP 128
#define PIX   4096          // 64*64
#define SKW   256
#define TMW   128

// Output region offsets (in elements)
#define OFF_RGB   0
#define OFF_SHADE 1572864
#define OFF_SPEC  2097152
#define OFF_BLOOD 3670016
#define OFF_MEL   4194304
#define OFF_B     4718592
#define OFF_RAW   4718848

__constant__ float c_S0[33] = {
    94.8f,104.8f,105.9f,96.8f,113.9f,125.6f,125.5f,121.3f,121.3f,113.5f,113.1f,
    110.8f,106.5f,108.8f,105.3f,104.4f,100.0f,96.0f,95.1f,89.1f,90.5f,90.3f,
    88.4f,84.0f,85.1f,81.9f,82.6f,84.9f,81.3f,71.9f,74.3f,76.4f,63.3f};
__constant__ float c_S1[33] = {
    43.4f,46.3f,43.9f,37.1f,36.7f,35.9f,32.6f,27.9f,24.3f,20.1f,16.2f,13.2f,
    8.6f,6.1f,4.2f,1.9f,0.0f,-1.6f,-3.5f,-3.5f,-5.8f,-7.2f,-8.6f,-9.5f,-10.9f,
    -10.7f,-12.0f,-14.0f,-13.6f,-12.0f,-13.3f,-12.9f,-10.6f};
__constant__ float c_S2[33] = {
    -1.1f,-0.5f,-0.7f,-1.2f,-2.6f,-2.9f,-2.8f,-2.6f,-2.6f,-1.8f,-1.5f,-1.3f,
    -1.2f,-1.0f,-0.5f,-0.3f,0.0f,0.2f,0.5f,2.1f,3.2f,4.1f,4.7f,5.1f,6.7f,7.3f,
    8.6f,9.8f,10.2f,8.3f,9.6f,8.5f,7.0f};
__constant__ float c_X2R[9] = {
    3.2406f,-1.537f,-0.498f, -0.968f,1.8758f,0.0415f, 0.0557f,-0.204f,1.057f};

// Per-sample folded constants: M[c][k] = e[k]*S[c][k] (padded to 40),
// lightColor[3], A[o][c]. 132 floats, copied flat to shared by main kernel.
struct SampleConst {
    float M[3][40];   // 120 (channels 33..39 zero)
    float lc[3];      // 3   (index 120..122)
    float A[9];       // 9   (index 123..131)
};
#define SC_FLOATS 132
__device__ SampleConst g_sc[NSAMP];

// fp16 channel-minor table: [256][256] texels x 40 halves (80 B = 5 uint4).
// Channels 33..39 are zero padding.
__device__ uint4 g_tab_h[SKW * SKW * 5];

__device__ __forceinline__ float sigmoidf_(float v) {
    return 1.0f / (1.0f + expf(-v));
}

// ---------------------------------------------------------------------------
// Kernel A: per-sample constants. Block per sample (128 blocks x 64 threads).
// Scalar parts computed redundantly by all threads (uniform); per-channel
// work spread across threads; reductions are deterministic serial sums.
// ---------------------------------------------------------------------------
__global__ void __launch_bounds__(64) setup_kernel(
    const float* __restrict__ lighting,
    const float* __restrict__ illA,
    const float* __restrict__ illF,
    const float* __restrict__ pcaMeans,
    const float* __restrict__ pcaComp,
    const float* __restrict__ tmatrix,
    float* __restrict__ out)
{
    int n = blockIdx.x;
    int tid = threadIdx.x;

    __shared__ float sL[17];
    __shared__ float s_dd[33];
    __shared__ float s_e[33];
    __shared__ float s_S[99];
    __shared__ float s_T[9];

    if (tid < 17) sL[tid] = lighting[n * 17 + tid];
    __syncthreads();

    // softmax over sL[0..13] (redundant per thread, uniform)
    float mx = sL[0];
    #pragma unroll
    for (int i = 1; i < 14; i++) mx = fmaxf(mx, sL[i]);
    float ex[14], ssum = 0.0f;
    #pragma unroll
    for (int i = 0; i < 14; i++) { ex[i] = expf(sL[i] - mx); ssum += ex[i]; }
    float sinv = 1.0f / ssum;
    float wA = ex[0] * sinv;
    float wD = ex[1] * sinv;
    float fW[12];
    #pragma unroll
    for (int j = 0; j < 12; j++) fW[j] = ex[2 + j] * sinv;

    float ct = sigmoidf_(sL[14]);
    float b0 = 6.0f * sigmoidf_(sL[15]) - 3.0f;
    float b1 = 6.0f * sigmoidf_(sL[16]) - 3.0f;
    if (tid == 0) {
        out[OFF_B + n * 2 + 0] = b0;
        out[OFF_B + n * 2 + 1] = b1;
    }

    // illuminance_d scalars (redundant, uniform branch)
    float t = ct * 21000.0f + 4000.0f;
    float t2 = t * t, t3 = t2 * t;
    float x;
    if (t <= 7000.0f)
        x = -4.607e9f / t3 + 2.9678e6f / t2 + 99.11f / t + 0.244063f;
    else
        x = -2.0064e9f / t3 + 1.9018e6f / t2 + 247.48f / t + 0.23704f;
    float y  = -3.0f * x * x + 2.87f * x - 0.275f;
    float mm = 0.0241f + 0.2562f * x - 0.7341f * y;
    float m1 = (-1.3515f - 1.7703f * x + 5.9114f * y) / mm;
    float m2 = (0.03f - 31.4424f * x + 30.0717f * y) / mm;

    if (tid < 33)
        s_dd[tid] = c_S0[tid] + m1 * c_S1[tid] + m2 * c_S2[tid];
    __syncthreads();

    float dsum = 0.0f;
    #pragma unroll
    for (int k = 0; k < 33; k++) dsum += s_dd[k];
    float dinv = 1.0f / dsum;

    if (tid < 33) {
        float v = wA * illA[tid] + wD * s_dd[tid] * dinv;
        #pragma unroll
        for (int j = 0; j < 12; j++) v += fW[j] * illF[tid * 12 + j];
        s_e[tid] = v;
    }
    __syncthreads();

    float esum = 0.0f;
    #pragma unroll
    for (int k = 0; k < 33; k++) esum += s_e[k];
    float einv = 1.0f / esum;

    for (int i = tid; i < 99; i += 64) {
        float v = pcaMeans[i] + b0 * pcaComp[i * 2] + b1 * pcaComp[i * 2 + 1];
        s_S[i] = fmaxf(v, 0.0f);
    }
    __syncthreads();

    float lc0 = 0.0f, lc1 = 0.0f, lc2 = 0.0f;
    #pragma unroll
    for (int k = 0; k < 33; k++) {
        lc0 += s_S[k];
        lc1 += s_S[33 + k];
        lc2 += s_S[66 + k];
    }

    SampleConst* sc = &g_sc[n];
    for (int idx = tid; idx < 120; idx += 64) {
        int c = idx / 40, k = idx % 40;
        ((float*)sc->M)[idx] = (k < 33) ? s_e[k] * einv * s_S[c * 33 + k] : 0.0f;
    }
    if (tid == 0) { sc->lc[0] = lc0; sc->lc[1] = lc1; sc->lc[2] = lc2; }

    // bilinear sample of tmatrix at (b/3)
    float gx = (b0 * (1.0f / 3.0f) + 1.0f) * 0.5f * 127.0f;
    float gy = (b1 * (1.0f / 3.0f) + 1.0f) * 0.5f * 127.0f;
    float x0f = floorf(gx), y0f = floorf(gy);
    float wx = gx - x0f, wy = gy - y0f;
    int x0 = min(max((int)x0f, 0), 127);
    int y0 = min(max((int)y0f, 0), 127);
    int x1 = min(x0 + 1, 127);
    int y1 = min(y0 + 1, 127);
    float w00 = (1.0f - wx) * (1.0f - wy);
    float w01 = wx * (1.0f - wy);
    float w10 = (1.0f - wx) * wy;
    float w11 = wx * wy;

    if (tid < 9) {
        const float* im = tmatrix + tid * TMW * TMW;
        s_T[tid] = im[y0 * TMW + x0] * w00 + im[y0 * TMW + x1] * w01
                 + im[y1 * TMW + x0] * w10 + im[y1 * TMW + x1] * w11;
    }
    __syncthreads();

    if (tid < 9) {
        int o = tid / 3, c = tid % 3;
        float lcc = (c == 0) ? lc0 : ((c == 1) ? lc1 : lc2);
        float v = c_X2R[o * 3 + 0] * s_T[c * 3 + 0]
                + c_X2R[o * 3 + 1] * s_T[c * 3 + 1]
                + c_X2R[o * 3 + 2] * s_T[c * 3 + 2];
        sc->A[tid] = v / lcc;
    }
}

// ---------------------------------------------------------------------------
// Kernel B: transpose skinColor [33,256,256] -> fp16 [256,256,40]
// ---------------------------------------------------------------------------
__global__ void transpose_kernel(const float* __restrict__ skin)
{
    int x = threadIdx.x;   // 0..255 (coalesced reads along x)
    int y = blockIdx.x;    // 0..255
    __align__(16) __half h[40];
    #pragma unroll
    for (int k = 0; k < 33; k++)
        h[k] = __float2half(skin[k * (SKW * SKW) + y * SKW + x]);
    #pragma unroll
    for (int k = 33; k < 40; k++) h[k] = __float2half(0.0f);

    const uint4* hv = reinterpret_cast<const uint4*>(h);
    uint4* dst = &g_tab_h[(y * SKW + x) * 5];
    #pragma unroll
    for (int q = 0; q < 5; q++) dst[q] = hv[q];
}

// ---------------------------------------------------------------------------
// Kernel C: per-pixel main. 16 blocks of 256 threads per sample.
// Gather: 4 corners x 5 uint4 (fp16) = 20 loads/pixel; math in f32.
// ---------------------------------------------------------------------------
__global__ void __launch_bounds__(256) main_kernel(
    const float* __restrict__ mel,
    const float* __restrict__ blood,
    const float* __restrict__ shade,
    const float* __restrict__ spec,
    float* __restrict__ out)
{
    __shared__ float sc[SC_FLOATS];   // M[3][40] | lc[3] | A[9]
    int n = blockIdx.x >> 4;
    int p = ((blockIdx.x & 15) << 8) + threadIdx.x;

    if (threadIdx.x < SC_FLOATS)
        sc[threadIdx.x] = ((const float*)&g_sc[n])[threadIdx.x];
    __syncthreads();

    int gi = n * PIX + p;
    float mraw = mel[gi];
    float braw = blood[gi];
    float sm = sigmoidf_(mraw);
    float sb = sigmoidf_(braw);
    float ms = 2.0f * sm - 1.0f;
    float bs = 2.0f * sb - 1.0f;
    float sh = expf(shade[gi]);

    float x = sm * 255.0f;
    float y = sb * 255.0f;
    float x0f = floorf(x), y0f = floorf(y);
    float wx = x - x0f, wy = y - y0f;
    int x0 = min(max((int)x0f, 0), 255);
    int y0 = min(max((int)y0f, 0), 255);
    int x1 = min(x0 + 1, 255);
    int y1 = min(y0 + 1, 255);
    float w00 = (1.0f - wx) * (1.0f - wy);
    float w01 = wx * (1.0f - wy);
    float w10 = (1.0f - wx) * wy;
    float w11 = wx * wy;

    const uint4* t00 = &g_tab_h[(y0 * SKW + x0) * 5];
    const uint4* t01 = &g_tab_h[(y0 * SKW + x1) * 5];
    const uint4* t10 = &g_tab_h[(y1 * SKW + x0) * 5];
    const uint4* t11 = &g_tab_h[(y1 * SKW + x1) * 5];

    float acc[40];
    #pragma unroll
    for (int k = 0; k < 40; k++) acc[k] = 0.0f;

    const uint4* tp[4] = {t00, t01, t10, t11};
    float     wc[4] = {w00, w01, w10, w11};
    #pragma unroll
    for (int c4 = 0; c4 < 4; c4++) {
        const uint4* tp_ = tp[c4];
        float w = wc[c4];
        #pragma unroll
        for (int i = 0; i < 5; i++) {
            uint4 u = __ldg(tp_ + i);
            const __half2* hh = reinterpret_cast<const __half2*>(&u);
            #pragma unroll
            for (int j = 0; j < 4; j++) {
                float2 f = __half22float2(hh[j]);
                acc[i * 8 + j * 2 + 0] += w * f.x;
                acc[i * 8 + j * 2 + 1] += w * f.y;
            }
        }
    }

    float d0 = 0.0f, d1 = 0.0f, d2 = 0.0f;
    #pragma unroll
    for (int k = 0; k < 40; k++) {
        d0 += acc[k] * sc[k];
        d1 += acc[k] * sc[40 + k];
        d2 += acc[k] * sc[80 + k];
    }
    d0 *= sh; d1 *= sh; d2 *= sh;

    float lc0 = sc[120], lc1 = sc[121], lc2 = sc[122];
    float sp0 = expf(spec[(n * 3 + 0) * PIX + p]) * lc0;
    float sp1 = expf(spec[(n * 3 + 1) * PIX + p]) * lc1;
    float sp2 = expf(spec[(n * 3 + 2) * PIX + p]) * lc2;

    float r0 = d0 + sp0;
    float r1 = d1 + sp1;
    float r2 = d2 + sp2;

    float g0 = fmaxf(sc[123] * r0 + sc[124] * r1 + sc[125] * r2, 0.0f);
    float g1 = fmaxf(sc[126] * r0 + sc[127] * r1 + sc[128] * r2, 0.0f);
    float g2 = fmaxf(sc[129] * r0 + sc[130] * r1 + sc[131] * r2, 0.0f);

    int c3 = n * 3 * PIX + p;
    out[OFF_RGB + c3]            = g0;
    out[OFF_RGB + c3 + PIX]      = g1;
    out[OFF_RGB + c3 + 2 * PIX]  = g2;
    out[OFF_SHADE + gi] = sh;
    out[OFF_SPEC + c3]           = sp0;
    out[OFF_SPEC + c3 + PIX]     = sp1;
    out[OFF_SPEC + c3 + 2 * PIX] = sp2;
    out[OFF_BLOOD + gi] = bs;
    out[OFF_MEL + gi]   = ms;
    out[OFF_RAW + c3]            = r0;
    out[OFF_RAW + c3 + PIX]      = r1;
    out[OFF_RAW + c3 + 2 * PIX]  = r2;
}

// ---------------------------------------------------------------------------
extern "C" void kernel_launch(void* const* d_in, const int* in_sizes, int n_in,
                              void* d_out, int out_size)
{
    const float* lighting = (const float*)d_in[0];
    const float* mel      = (const float*)d_in[1];
    const float* blood    = (const float*)d_in[2];
    const float* shade    = (const float*)d_in[3];
    const float* spec     = (const float*)d_in[4];
    const float* illA     = (const float*)d_in[5];
    const float* illF     = (const float*)d_in[6];
    const float* pcaMeans = (const float*)d_in[7];
    const float* pcaComp  = (const float*)d_in[8];
    const float* skin     = (const float*)d_in[9];
    const float* tmatrix  = (const float*)d_in[10];
    float* out = (float*)d_out;

    setup_kernel<<<NSAMP, 64>>>(lighting, illA, illF, pcaMeans, pcaComp, tmatrix, out);
    transpose_kernel<<<256, 256>>>(skin);
    main_kernel<<<(NSAMP * PIX) / 256, 256>>>(mel, blood, shade, spec, out);
}